// round 4
// baseline (speedup 1.0000x reference)
#include <cuda_runtime.h>
#include <math.h>

#define B_ 16
#define N_ 2304
#define D_ 1024
#define H_ 1344
#define W_ 1344
#define M_ 8
#define HV_ 48
#define PH_ 28
#define NRAYS 24
#define NSAMP 20

#define NCH2 18           // chunks for rgb pass
#define CH2 128           // tokens per chunk
#define SUBT 8            // tokens per subtile
#define NSUB 16           // subtiles per chunk

#define RG_ 168           // row groups (H/8)
#define ROWS_PER_BLK 8

// ---------------- scratch ----------------
__device__ unsigned char g_packed[H_ * W_];
__device__ int           g_patchsum[M_ * N_];
__device__ float         g_soft2d[M_ * N_];
__device__ float         g_logsoft[M_ * N_];
__device__ float         g_msc[M_ * 8];
__device__ float         g_rowd[M_ * B_ * RG_];
__device__ float         g_rowd2[M_ * B_ * RG_];
__device__ float         g_partial[NCH2 * M_ * B_ * D_];   // 9.4 MB
__device__ float         g_locmax[NCH2 * M_ * B_];
__device__ float         g_locsum[NCH2 * M_ * B_];

// ---------------- helpers ----------------
__device__ __forceinline__ float blockSum(float v, float* sm) {
    int lane = threadIdx.x & 31, w = threadIdx.x >> 5;
    int nw = blockDim.x >> 5;
#pragma unroll
    for (int o = 16; o; o >>= 1) v += __shfl_down_sync(0xffffffffu, v, o);
    if (lane == 0) sm[w] = v;
    __syncthreads();
    if (w == 0) {
        v = (lane < nw) ? sm[lane] : 0.f;
#pragma unroll
        for (int o = 16; o; o >>= 1) v += __shfl_down_sync(0xffffffffu, v, o);
        if (lane == 0) sm[0] = v;
    }
    __syncthreads();
    float r = sm[0];
    __syncthreads();
    return r;
}

#define CP_ASYNC16(dst_smem_u32, src) \
    asm volatile("cp.async.cg.shared.global [%0], [%1], 16;" :: "r"(dst_smem_u32), "l"(src))
#define CP_COMMIT() asm volatile("cp.async.commit_group;")
#define CP_WAIT1() asm volatile("cp.async.wait_group 1;")
#define CP_WAIT0() asm volatile("cp.async.wait_group 0;")

// ---------------- K2: mask bitpack + per-patch sums ----------------
__global__ void k2_mask(const int* __restrict__ masks) {
    int p = blockIdx.x;
    int py = p / HV_, px = p % HV_;
    int tid = threadIdx.x;          // 256
    int sums[M_];
#pragma unroll
    for (int m = 0; m < M_; m++) sums[m] = 0;

    if (tid < 196) {
        int row = tid / 7, g = tid % 7;
        int y = py * PH_ + row;
        int x = px * PH_ + g * 4;
        unsigned b0 = 0, b1 = 0, b2 = 0, b3 = 0;
#pragma unroll
        for (int m = 0; m < M_; m++) {
            int4 v = *(const int4*)(masks + ((size_t)m * H_ + y) * W_ + x);
            int q0 = (v.x != 0), q1 = (v.y != 0), q2 = (v.z != 0), q3 = (v.w != 0);
            sums[m] = q0 + q1 + q2 + q3;
            b0 |= (unsigned)q0 << m; b1 |= (unsigned)q1 << m;
            b2 |= (unsigned)q2 << m; b3 |= (unsigned)q3 << m;
        }
        *(uchar4*)(g_packed + (size_t)y * W_ + x) =
            make_uchar4((unsigned char)b0, (unsigned char)b1, (unsigned char)b2, (unsigned char)b3);
    }

    __shared__ int ssum[8 * M_];
    int lane = tid & 31, w = tid >> 5;
#pragma unroll
    for (int m = 0; m < M_; m++) {
        int v = sums[m];
#pragma unroll
        for (int o = 16; o; o >>= 1) v += __shfl_down_sync(0xffffffffu, v, o);
        if (lane == 0) ssum[w * M_ + m] = v;
    }
    __syncthreads();
    if (tid < M_) {
        int t = 0;
#pragma unroll
        for (int ww = 0; ww < 8; ww++) t += ssum[ww * M_ + tid];
        g_patchsum[tid * N_ + p] = t;
    }
}

// ---------------- K2b: soft2d / logsoft / per-mask scalars ----------------
__global__ void k2b_scalars() {
    int m = blockIdx.x;
    int tid = threadIdx.x;  // 256
    __shared__ float sm[32];
    float c = 0.f, ss = 0.f, sx = 0.f, sy = 0.f;
    for (int p = tid; p < N_; p += 256) {
        int ps = g_patchsum[m * N_ + p];
        float cov = (float)ps * (1.f / 784.f);
        float soft = 1.f / (1.f + expf(-50.f * (cov - 0.3f)));
        g_soft2d[m * N_ + p] = soft;
        g_logsoft[m * N_ + p] = logf(fmaxf(soft, 1e-8f));
        c += (float)ps;
        ss += soft;
        sx += soft * (float)(p % HV_);
        sy += soft * (float)(p / HV_);
    }
    c  = blockSum(c, sm);
    ss = blockSum(ss, sm);
    sx = blockSum(sx, sm);
    sy = blockSum(sy, sm);
    if (tid == 0) {
        float soft_sum = ss + 1e-8f;
        float cx = sx / (soft_sum * (float)HV_);
        float cy = sy / (soft_sum * (float)HV_);
        g_msc[m * 8 + 0] = c;
        g_msc[m * 8 + 1] = cx;
        g_msc[m * 8 + 2] = cy;
        g_msc[m * 8 + 3] = cx * (float)(W_ - 1);
        g_msc[m * 8 + 4] = cy * (float)(H_ - 1);
    }
}

// ---------------- K3: depth partials, 8 rows x 4 batches per block ----------------
__global__ void __launch_bounds__(256) k3_depth(const float* __restrict__ depth) {
    int rg = blockIdx.x;            // 0..167
    int bg = blockIdx.y;            // 0..3  (b = 4*bg .. 4*bg+3)
    int tid = threadIdx.x;          // 256
    int b0 = bg * 4;
    int row0 = rg * ROWS_PER_BLK;

    unsigned long long acc[32];     // [batch*8 + m]
#pragma unroll
    for (int i = 0; i < 32; i++) acc[i] = 0ull;

    const int NG = ROWS_PER_BLK * (W_ / 4);   // 2688 float4-groups
    for (int idx = tid; idx < NG; idx += 256) {
        int r = idx / (W_ / 4);
        int g = idx - r * (W_ / 4);
        int row = row0 + r;
        uchar4 p4 = ((const uchar4*)(g_packed + (size_t)row * W_))[g];
        float4 dA = ((const float4*)(depth + ((size_t)(b0 + 0) * H_ + row) * W_))[g];
        float4 dB = ((const float4*)(depth + ((size_t)(b0 + 1) * H_ + row) * W_))[g];
        float4 dC = ((const float4*)(depth + ((size_t)(b0 + 2) * H_ + row) * W_))[g];
        float4 dD = ((const float4*)(depth + ((size_t)(b0 + 3) * H_ + row) * W_))[g];
        unsigned pb[4] = {p4.x, p4.y, p4.z, p4.w};
        float vA[4] = {dA.x, dA.y, dA.z, dA.w};
        float vB[4] = {dB.x, dB.y, dB.z, dB.w};
        float vC[4] = {dC.x, dC.y, dC.z, dC.w};
        float vD[4] = {dD.x, dD.y, dD.z, dD.w};
#pragma unroll
        for (int k = 0; k < 4; k++) {
            unsigned long long pA, pB, pC, pD;
            asm("mov.b64 %0, {%1, %2};" : "=l"(pA)
                : "r"(__float_as_uint(vA[k])), "r"(__float_as_uint(vA[k] * vA[k])));
            asm("mov.b64 %0, {%1, %2};" : "=l"(pB)
                : "r"(__float_as_uint(vB[k])), "r"(__float_as_uint(vB[k] * vB[k])));
            asm("mov.b64 %0, {%1, %2};" : "=l"(pC)
                : "r"(__float_as_uint(vC[k])), "r"(__float_as_uint(vC[k] * vC[k])));
            asm("mov.b64 %0, {%1, %2};" : "=l"(pD)
                : "r"(__float_as_uint(vD[k])), "r"(__float_as_uint(vD[k] * vD[k])));
            unsigned pbk = pb[k];
#pragma unroll
            for (int m = 0; m < M_; m++) {
                asm volatile(
                    "{ .reg .pred p; setp.ne.u32 p, %4, 0;\n\t"
                    "  @p add.rn.f32x2 %0, %0, %5;\n\t"
                    "  @p add.rn.f32x2 %1, %1, %6;\n\t"
                    "  @p add.rn.f32x2 %2, %2, %7;\n\t"
                    "  @p add.rn.f32x2 %3, %3, %8; }"
                    : "+l"(acc[m]), "+l"(acc[8 + m]), "+l"(acc[16 + m]), "+l"(acc[24 + m])
                    : "r"(pbk & (1u << m)), "l"(pA), "l"(pB), "l"(pC), "l"(pD));
            }
        }
    }

    __shared__ unsigned long long sred[8][32];
    int lane = tid & 31, w = tid >> 5;
#pragma unroll
    for (int i = 0; i < 32; i++) {
        unsigned long long v = acc[i];
#pragma unroll
        for (int o = 16; o; o >>= 1) {
            unsigned long long u = __shfl_down_sync(0xffffffffu, v, o);
            asm("add.rn.f32x2 %0, %0, %1;" : "+l"(v) : "l"(u));
        }
        if (lane == 0) sred[w][i] = v;
    }
    __syncthreads();
    if (tid < 32) {
        float sd = 0.f, sd2 = 0.f;
#pragma unroll
        for (int ww = 0; ww < 8; ww++) {
            unsigned lo, hi;
            asm("mov.b64 {%0, %1}, %2;" : "=r"(lo), "=r"(hi) : "l"(sred[ww][tid]));
            sd  += __uint_as_float(lo);
            sd2 += __uint_as_float(hi);
        }
        int b = b0 + (tid >> 3);
        int m = tid & 7;
        g_rowd[((size_t)m * B_ + b) * RG_ + rg]  = sd;
        g_rowd2[((size_t)m * B_ + b) * RG_ + rg] = sd2;
    }
}

// ---------------- K5: fused scores + online softmax + weighted sum ----------------
// grid (NCH2, B), 512 threads, 2 CTAs/SM.
// smem: [gw 1024][buf0 8192][buf1 8192][schalf 16][e 8*8][scale 8]
__global__ void __launch_bounds__(512, 2) k5_fused(const float* __restrict__ tok,
                                                   const float* __restrict__ gw) {
    extern __shared__ float smem[];
    float* s_gw     = smem;                       // 1024
    float* s_buf    = smem + 1024;                // 2 x 8192
    float* s_schalf = smem + 1024 + 2 * 8192;     // 16
    float* s_e      = s_schalf + 16;              // [SUBT][8]
    float* s_scale  = s_e + SUBT * 8;             // 8

    int c = blockIdx.x, b = blockIdx.y;
    int tid = threadIdx.x;
    int lane = tid & 31, w = tid >> 5;            // 16 warps
    const float* gtok = tok + ((size_t)b * N_ + (size_t)c * CH2) * D_;

    ((float2*)s_gw)[tid] = ((const float2*)gw)[tid];

    // prologue: async copy subtile 0 (8 tokens = 8192 floats = 2048 float4)
    {
        unsigned dst = (unsigned)__cvta_generic_to_shared(s_buf) + tid * 16;
#pragma unroll
        for (int i = 0; i < 4; i++)
            CP_ASYNC16(dst + i * 512 * 16, (const float4*)gtok + tid + i * 512);
        CP_COMMIT();
    }

    float2 acc2[M_];
#pragma unroll
    for (int m = 0; m < M_; m++) acc2[m] = make_float2(0.f, 0.f);
    float rm = -3.0e38f, rs = 0.f;                // warps 0..7: online softmax state

    for (int t = 0; t < NSUB; t++) {
        float* buf = s_buf + (t & 1) * 8192;
        if (t + 1 < NSUB) {
            float* nbuf = s_buf + ((t + 1) & 1) * 8192;
            unsigned dst = (unsigned)__cvta_generic_to_shared(nbuf) + tid * 16;
            const float4* src = (const float4*)(gtok + (size_t)(t + 1) * SUBT * D_) + tid;
#pragma unroll
            for (int i = 0; i < 4; i++)
                CP_ASYNC16(dst + i * 512 * 16, src + i * 512);
            CP_COMMIT();
            CP_WAIT1();
        } else {
            CP_WAIT0();
        }
        __syncthreads();

        // dots: warp w owns half (w&1) of token (w>>1); 16 warps fully used
        {
            int tok_j = w >> 1, half = w & 1;
            const float4* tp = (const float4*)(buf + (size_t)tok_j * D_ + half * 512);
            const float4* gp = (const float4*)(s_gw + half * 512);
            float acc = 0.f;
#pragma unroll
            for (int it = 0; it < 4; it++) {
                float4 a = tp[lane + it * 32];
                float4 g = gp[lane + it * 32];
                acc += a.x * g.x + a.y * g.y + a.z * g.z + a.w * g.w;
            }
#pragma unroll
            for (int o = 16; o; o >>= 1) acc += __shfl_down_sync(0xffffffffu, acc, o);
            if (lane == 0) s_schalf[w] = acc;
        }
        __syncthreads();

        // online softmax: warp m (<8), lanes 0..7 = tokens
        if (w < 8) {
            int m = w;
            float v = -3.0e38f;
            if (lane < SUBT)
                v = s_schalf[2 * lane] + s_schalf[2 * lane + 1]
                  + g_logsoft[m * N_ + c * CH2 + t * SUBT + lane];
            float mx = v;
#pragma unroll
            for (int o = 16; o; o >>= 1) mx = fmaxf(mx, __shfl_xor_sync(0xffffffffu, mx, o));
            float nm = fmaxf(rm, mx);
            float sc = expf(rm - nm);
            float e = (lane < SUBT) ? expf(v - nm) : 0.f;
            if (lane < SUBT) s_e[lane * 8 + m] = e;
            float se = e;
#pragma unroll
            for (int o = 16; o; o >>= 1) se += __shfl_xor_sync(0xffffffffu, se, o);
            rs = rs * sc + se;
            rm = nm;
            if (lane == 0) s_scale[m] = sc;
        }
        __syncthreads();

        // accumulate: thread owns d-pair [2*tid, 2*tid+1]
        {
#pragma unroll
            for (int m = 0; m < M_; m++) {
                float sc = s_scale[m];
                acc2[m].x *= sc; acc2[m].y *= sc;
            }
#pragma unroll
            for (int j = 0; j < SUBT; j++) {
                float2 tv = *(const float2*)(buf + (size_t)j * D_ + tid * 2);
                float4 e0 = *(const float4*)(s_e + j * 8);
                float4 e1 = *(const float4*)(s_e + j * 8 + 4);
                acc2[0].x = fmaf(e0.x, tv.x, acc2[0].x); acc2[0].y = fmaf(e0.x, tv.y, acc2[0].y);
                acc2[1].x = fmaf(e0.y, tv.x, acc2[1].x); acc2[1].y = fmaf(e0.y, tv.y, acc2[1].y);
                acc2[2].x = fmaf(e0.z, tv.x, acc2[2].x); acc2[2].y = fmaf(e0.z, tv.y, acc2[2].y);
                acc2[3].x = fmaf(e0.w, tv.x, acc2[3].x); acc2[3].y = fmaf(e0.w, tv.y, acc2[3].y);
                acc2[4].x = fmaf(e1.x, tv.x, acc2[4].x); acc2[4].y = fmaf(e1.x, tv.y, acc2[4].y);
                acc2[5].x = fmaf(e1.y, tv.x, acc2[5].x); acc2[5].y = fmaf(e1.y, tv.y, acc2[5].y);
                acc2[6].x = fmaf(e1.z, tv.x, acc2[6].x); acc2[6].y = fmaf(e1.z, tv.y, acc2[6].y);
                acc2[7].x = fmaf(e1.w, tv.x, acc2[7].x); acc2[7].y = fmaf(e1.w, tv.y, acc2[7].y);
            }
        }
        __syncthreads();
    }

#pragma unroll
    for (int m = 0; m < M_; m++)
        *(float2*)&g_partial[(((size_t)c * M_ + m) * B_ + b) * D_ + tid * 2] = acc2[m];
    if (w < 8 && lane == 0) {
        int idx = (c * M_ + w) * B_ + b;
        g_locmax[idx] = rm;
        g_locsum[idx] = rs;
    }
}

// ---------------- K6: combine partials -> rgb out ----------------
__global__ void k6_combine(float* __restrict__ out) {
    int mb = blockIdx.x;            // m*B + b
    int m = mb / B_, b = mb % B_;
    int tid = threadIdx.x;          // 256
    __shared__ float s_scale[NCH2];
    __shared__ float s_invS;
    if (tid == 0) {
        float MX = -1e30f;
#pragma unroll
        for (int c = 0; c < NCH2; c++)
            MX = fmaxf(MX, g_locmax[(c * M_ + m) * B_ + b]);
        float S = 0.f;
#pragma unroll
        for (int c = 0; c < NCH2; c++) {
            float sc = expf(g_locmax[(c * M_ + m) * B_ + b] - MX);
            s_scale[c] = sc;
            S += sc * g_locsum[(c * M_ + m) * B_ + b];
        }
        s_invS = 1.f / S;
    }
    __syncthreads();
    float4 a = make_float4(0.f, 0.f, 0.f, 0.f);
#pragma unroll
    for (int c = 0; c < NCH2; c++) {
        float sc = s_scale[c];
        float4 p = ((const float4*)&g_partial[(((size_t)c * M_ + m) * B_ + b) * D_])[tid];
        a.x = fmaf(sc, p.x, a.x);
        a.y = fmaf(sc, p.y, a.y);
        a.z = fmaf(sc, p.z, a.z);
        a.w = fmaf(sc, p.w, a.w);
    }
    float inv = s_invS;
    a.x *= inv; a.y *= inv; a.z *= inv; a.w *= inv;
    ((float4*)&out[((size_t)m * B_ + b) * D_])[tid] = a;
}

// ---------------- bilinear helpers ----------------
__device__ __forceinline__ float bilin_border(const float* img, float x, float y) {
    x = fminf(fmaxf(x, 0.f), (float)(W_ - 1));
    y = fminf(fmaxf(y, 0.f), (float)(H_ - 1));
    float x0f = floorf(x), y0f = floorf(y);
    float wx = x - x0f, wy = y - y0f;
    int x0 = (int)x0f, y0 = (int)y0f;
    int x1 = min(x0 + 1, W_ - 1), y1 = min(y0 + 1, H_ - 1);
    return img[y0 * W_ + x0] * (1.f - wx) * (1.f - wy)
         + img[y0 * W_ + x1] * wx * (1.f - wy)
         + img[y1 * W_ + x0] * (1.f - wx) * wy
         + img[y1 * W_ + x1] * wx * wy;
}

__device__ __forceinline__ float tap48(const float* img, int yy, int xx, float w) {
    if (xx >= 0 && xx < HV_ && yy >= 0 && yy < HV_) return img[yy * HV_ + xx] * w;
    return 0.f;
}

__device__ __forceinline__ float bilin_zeros48(const float* img, float x, float y) {
    float x0f = floorf(x), y0f = floorf(y);
    float wx = x - x0f, wy = y - y0f;
    int x0 = (int)x0f, y0 = (int)y0f;
    float v = tap48(img, y0, x0, (1.f - wx) * (1.f - wy));
    v += tap48(img, y0, x0 + 1, wx * (1.f - wy));
    v += tap48(img, y0 + 1, x0, (1.f - wx) * wy);
    v += tap48(img, y0 + 1, x0 + 1, wx * wy);
    return v;
}

// ---------------- K7: rays + stats + GEMV + layernorm ----------------
__global__ void k7_dep(const float* __restrict__ depth,
                       const float* __restrict__ dw, const float* __restrict__ db,
                       const float* __restrict__ gamma, const float* __restrict__ beta,
                       float* __restrict__ out) {
    int b = blockIdx.x, m = blockIdx.y;
    int tid = threadIdx.x;  // 512
    __shared__ float sm[32];
    __shared__ float s_stats[28];
    __shared__ float s_ds[NRAYS * NSAMP];
    __shared__ float s_sw[NRAYS * NSAMP];

    float a = 0.f, a2 = 0.f;
    if (tid < RG_) {
        a  = g_rowd[((size_t)m * B_ + b) * RG_ + tid];
        a2 = g_rowd2[((size_t)m * B_ + b) * RG_ + tid];
    }
    float sum_d  = blockSum(a, sm);
    float sum_d2 = blockSum(a2, sm);

    float count = g_msc[m * 8 + 0];
    float cx    = g_msc[m * 8 + 1];
    float cy    = g_msc[m * 8 + 2];
    float cxp   = g_msc[m * 8 + 3];
    float cyp   = g_msc[m * 8 + 4];

    float mean_d = sum_d / fmaxf(count, 1.f);
    float var = (sum_d2 - count * mean_d * mean_d) / fmaxf(count - 1.f, 1.f);
    float std_d = (count > 1.f) ? sqrtf(fmaxf(var, 0.f)) : 0.f;

    if (tid < NRAYS * NSAMP) {
        int r = tid / NSAMP, s = tid % NSAMP;
        double ang = (2.0 * 3.14159265358979323846 / (double)NRAYS) * (double)r;
        float ca = (float)cos(ang), sa = (float)sin(ang);
        float tv = (float)(((double)(W_ < H_ ? W_ : H_) * 0.45 / (double)(NSAMP - 1)) * (double)s);
        float x = cxp + ca * tv;
        float y = cyp + sa * tv;
        const float* dm = depth + (size_t)b * H_ * W_;
        s_ds[tid] = bilin_border(dm, x, y);
        float xp = x / (float)(W_ - 1) * (float)(HV_ - 1);
        float yp = y / (float)(H_ - 1) * (float)(HV_ - 1);
        float sw = bilin_zeros48(g_soft2d + m * N_, xp, yp);
        s_sw[tid] = fmaxf(sw, 1e-6f);
    }
    __syncthreads();

    if (tid < NRAYS) {
        float ws = 0.f, pr = 0.f;
#pragma unroll
        for (int s = 0; s < NSAMP; s++) {
            ws += s_sw[tid * NSAMP + s];
            pr += s_ds[tid * NSAMP + s] * s_sw[tid * NSAMP + s];
        }
        float ok = (count > 0.f) ? 1.f : 0.f;
        s_stats[4 + tid] = (pr / ws) * ok;
    }
    if (tid == 0) {
        float ok = (count > 0.f) ? 1.f : 0.f;
        s_stats[0] = mean_d * ok;
        s_stats[1] = std_d * ok;
        s_stats[2] = cx * ok;
        s_stats[3] = cy * ok;
    }
    __syncthreads();

    float h0 = db[tid], h1 = db[tid + 512];
#pragma unroll
    for (int k = 0; k < 28; k++) {
        float st = s_stats[k];
        h0 = fmaf(st, dw[k * D_ + tid], h0);
        h1 = fmaf(st, dw[k * D_ + tid + 512], h1);
    }
    float mu = blockSum(h0 + h1, sm) * (1.f / (float)D_);
    float e0 = h0 - mu, e1 = h1 - mu;
    float v2 = blockSum(e0 * e0 + e1 * e1, sm) * (1.f / (float)D_);
    float inv = rsqrtf(v2 + 1e-5f);
    size_t off = (size_t)(M_ * B_ * D_) + ((size_t)m * B_ + b) * D_;
    out[off + tid]       = e0 * inv * gamma[tid] + beta[tid];
    out[off + tid + 512] = e1 * inv * gamma[tid + 512] + beta[tid + 512];
}

// ---------------- launch ----------------
#define K5_SMEM ((1024 + 2 * 8192 + 16 + SUBT * 8 + 8) * 4)

extern "C" void kernel_launch(void* const* d_in, const int* in_sizes, int n_in,
                              void* d_out, int out_size) {
    const float* tok   = (const float*)d_in[0];
    const float* depth = (const float*)d_in[1];
    const int*   masks = (const int*)d_in[2];
    const float* gw    = (const float*)d_in[3];
    const float* dw    = (const float*)d_in[4];
    const float* db    = (const float*)d_in[5];
    const float* gamma = (const float*)d_in[6];
    const float* beta  = (const float*)d_in[7];
    float* out = (float*)d_out;

    cudaFuncSetAttribute(k5_fused, cudaFuncAttributeMaxDynamicSharedMemorySize, K5_SMEM);

    k2_mask<<<N_, 256>>>(masks);
    k2b_scalars<<<M_, 256>>>();
    k5_fused<<<dim3(NCH2, B_), 512, K5_SMEM>>>(tok, gw);
    k3_depth<<<dim3(RG_, B_ / 4), 256>>>(depth);
    k6_combine<<<M_ * B_, 256>>>(out);
    k7_dep<<<dim3(B_, M_), 512>>>(depth, dw, db, gamma, beta, out);
}

// round 5
// speedup vs baseline: 1.1899x; 1.1899x over previous
#include <cuda_runtime.h>
#include <math.h>

#define B_ 16
#define N_ 2304
#define D_ 1024
#define H_ 1344
#define W_ 1344
#define M_ 8
#define HV_ 48
#define PH_ 28
#define NRAYS 24
#define NSAMP 20

#define NCH2 18           // chunks for rgb pass
#define CH2 128           // tokens per chunk
#define SUBT 8            // tokens per subtile
#define NSUB 16           // subtiles per chunk

#define K3_TILE 512
#define K3_TPB 8                      // tiles per block
#define K3_BLOCKS 441                 // 441*8*512 = 1806336 = H*W

// ---------------- scratch ----------------
__device__ unsigned char g_packed[H_ * W_];
__device__ int           g_patchsum[M_ * N_];
__device__ float         g_soft2d[M_ * N_];
__device__ float         g_logsoft[M_ * N_];
__device__ float         g_msc[M_ * 8];
__device__ float         g_part3[K3_BLOCKS][256];          // [type(2)][b(16)][m(8)]
__device__ float         g_partial[NCH2 * M_ * B_ * D_];   // 9.4 MB
__device__ float         g_locmax[NCH2 * M_ * B_];
__device__ float         g_locsum[NCH2 * M_ * B_];

// ---------------- helpers ----------------
__device__ __forceinline__ float blockSum(float v, float* sm) {
    int lane = threadIdx.x & 31, w = threadIdx.x >> 5;
    int nw = blockDim.x >> 5;
#pragma unroll
    for (int o = 16; o; o >>= 1) v += __shfl_down_sync(0xffffffffu, v, o);
    if (lane == 0) sm[w] = v;
    __syncthreads();
    if (w == 0) {
        v = (lane < nw) ? sm[lane] : 0.f;
#pragma unroll
        for (int o = 16; o; o >>= 1) v += __shfl_down_sync(0xffffffffu, v, o);
        if (lane == 0) sm[0] = v;
    }
    __syncthreads();
    float r = sm[0];
    __syncthreads();
    return r;
}

#define CP_ASYNC16(dst_smem_u32, src) \
    asm volatile("cp.async.cg.shared.global [%0], [%1], 16;" :: "r"(dst_smem_u32), "l"(src))
#define CP_COMMIT() asm volatile("cp.async.commit_group;")
#define CP_WAIT1() asm volatile("cp.async.wait_group 1;")
#define CP_WAIT0() asm volatile("cp.async.wait_group 0;")

__device__ __forceinline__ unsigned f2tf32(float f) {
    unsigned u;
    asm("cvt.rna.tf32.f32 %0, %1;" : "=r"(u) : "f"(f));
    return u;
}

__device__ __forceinline__ void mma_tf32(float* c, unsigned a0, unsigned a1,
                                         unsigned a2, unsigned a3,
                                         unsigned b0, unsigned b1) {
    asm volatile(
        "mma.sync.aligned.m16n8k8.row.col.f32.tf32.tf32.f32 "
        "{%0,%1,%2,%3}, {%4,%5,%6,%7}, {%8,%9}, {%0,%1,%2,%3};"
        : "+f"(c[0]), "+f"(c[1]), "+f"(c[2]), "+f"(c[3])
        : "r"(a0), "r"(a1), "r"(a2), "r"(a3), "r"(b0), "r"(b1));
}

// ---------------- K2: mask bitpack + per-patch sums ----------------
__global__ void k2_mask(const int* __restrict__ masks) {
    int p = blockIdx.x;
    int py = p / HV_, px = p % HV_;
    int tid = threadIdx.x;          // 256
    int sums[M_];
#pragma unroll
    for (int m = 0; m < M_; m++) sums[m] = 0;

    if (tid < 196) {
        int row = tid / 7, g = tid % 7;
        int y = py * PH_ + row;
        int x = px * PH_ + g * 4;
        unsigned b0 = 0, b1 = 0, b2 = 0, b3 = 0;
#pragma unroll
        for (int m = 0; m < M_; m++) {
            int4 v = *(const int4*)(masks + ((size_t)m * H_ + y) * W_ + x);
            int q0 = (v.x != 0), q1 = (v.y != 0), q2 = (v.z != 0), q3 = (v.w != 0);
            sums[m] = q0 + q1 + q2 + q3;
            b0 |= (unsigned)q0 << m; b1 |= (unsigned)q1 << m;
            b2 |= (unsigned)q2 << m; b3 |= (unsigned)q3 << m;
        }
        *(uchar4*)(g_packed + (size_t)y * W_ + x) =
            make_uchar4((unsigned char)b0, (unsigned char)b1, (unsigned char)b2, (unsigned char)b3);
    }

    __shared__ int ssum[8 * M_];
    int lane = tid & 31, w = tid >> 5;
#pragma unroll
    for (int m = 0; m < M_; m++) {
        int v = sums[m];
#pragma unroll
        for (int o = 16; o; o >>= 1) v += __shfl_down_sync(0xffffffffu, v, o);
        if (lane == 0) ssum[w * M_ + m] = v;
    }
    __syncthreads();
    if (tid < M_) {
        int t = 0;
#pragma unroll
        for (int ww = 0; ww < 8; ww++) t += ssum[ww * M_ + tid];
        g_patchsum[tid * N_ + p] = t;
    }
}

// ---------------- K2b: soft2d / logsoft / per-mask scalars ----------------
__global__ void k2b_scalars() {
    int m = blockIdx.x;
    int tid = threadIdx.x;  // 256
    __shared__ float sm[32];
    float c = 0.f, ss = 0.f, sx = 0.f, sy = 0.f;
    for (int p = tid; p < N_; p += 256) {
        int ps = g_patchsum[m * N_ + p];
        float cov = (float)ps * (1.f / 784.f);
        float soft = 1.f / (1.f + expf(-50.f * (cov - 0.3f)));
        g_soft2d[m * N_ + p] = soft;
        g_logsoft[m * N_ + p] = logf(fmaxf(soft, 1e-8f));
        c += (float)ps;
        ss += soft;
        sx += soft * (float)(p % HV_);
        sy += soft * (float)(p / HV_);
    }
    c  = blockSum(c, sm);
    ss = blockSum(ss, sm);
    sx = blockSum(sx, sm);
    sy = blockSum(sy, sm);
    if (tid == 0) {
        float soft_sum = ss + 1e-8f;
        float cx = sx / (soft_sum * (float)HV_);
        float cy = sy / (soft_sum * (float)HV_);
        g_msc[m * 8 + 0] = c;
        g_msc[m * 8 + 1] = cx;
        g_msc[m * 8 + 2] = cy;
        g_msc[m * 8 + 3] = cx * (float)(W_ - 1);
        g_msc[m * 8 + 4] = cy * (float)(H_ - 1);
    }
}

// ---------------- K3: depth stats via tf32 MMA ----------------
// D[16 batches x 8 masks] += A[16 x 8px](depth or depth^2) * B[8px x 8 masks](mask bits)
__global__ void __launch_bounds__(256) k3_mma(const float* __restrict__ depth) {
    __shared__ float sd[16][K3_TILE + 4];
    __shared__ unsigned char smask[K3_TILE];
    __shared__ float sredk[8][256];

    int tid = threadIdx.x;
    int lane = tid & 31, w = tid >> 5;    // 8 warps
    int gid = lane >> 2;                  // group id 0..7
    int tig = lane & 3;                   // thread in group 0..3

    float c_d[4]  = {0.f, 0.f, 0.f, 0.f};
    float c_d2[4] = {0.f, 0.f, 0.f, 0.f};

    for (int t = 0; t < K3_TPB; t++) {
        size_t px0 = ((size_t)blockIdx.x * K3_TPB + t) * K3_TILE;
        __syncthreads();   // protect smem from previous tile's readers
        // stage depth: 16 batches x 512 px, coalesced float4
#pragma unroll
        for (int i = 0; i < 8; i++) {
            int idx = tid + i * 256;              // 0..2047
            int b = idx >> 7;                     // /128
            int g = idx & 127;
            float4 v = *(const float4*)(depth + (size_t)b * (H_ * W_) + px0 + g * 4);
            *(float4*)&sd[b][g * 4] = v;
        }
        if (tid < 128) ((uchar4*)smask)[tid] = *(const uchar4*)(g_packed + px0 + tid * 4);
        __syncthreads();

        // warp w handles pixels [w*64, w*64+64): 8 k-steps of 8 pixels
        int pbase = w * 64;
#pragma unroll
        for (int s = 0; s < 8; s++) {
            int px = pbase + s * 8;
            float a0 = sd[gid][px + tig];
            float a1 = sd[gid + 8][px + tig];
            float a2 = sd[gid][px + 4 + tig];
            float a3 = sd[gid + 8][px + 4 + tig];
            unsigned ua0 = f2tf32(a0), ua1 = f2tf32(a1), ua2 = f2tf32(a2), ua3 = f2tf32(a3);
            unsigned uq0 = f2tf32(a0 * a0), uq1 = f2tf32(a1 * a1);
            unsigned uq2 = f2tf32(a2 * a2), uq3 = f2tf32(a3 * a3);
            unsigned byt0 = smask[px + tig];
            unsigned byt1 = smask[px + 4 + tig];
            unsigned b0 = ((byt0 >> gid) & 1u) ? 0x3F800000u : 0u;
            unsigned b1 = ((byt1 >> gid) & 1u) ? 0x3F800000u : 0u;
            mma_tf32(c_d,  ua0, ua1, ua2, ua3, b0, b1);
            mma_tf32(c_d2, uq0, uq1, uq2, uq3, b0, b1);
        }
    }

    // epilogue: D fragment -> smem -> cross-warp sum -> g_part3
    // c0: row=gid, col=2*tig ; c1: +1 col ; c2: row=gid+8 ; c3: row=gid+8, col+1
    int p00 = gid * 8 + 2 * tig;
    int p10 = (gid + 8) * 8 + 2 * tig;
    sredk[w][p00]       = c_d[0];
    sredk[w][p00 + 1]   = c_d[1];
    sredk[w][p10]       = c_d[2];
    sredk[w][p10 + 1]   = c_d[3];
    sredk[w][128 + p00]     = c_d2[0];
    sredk[w][128 + p00 + 1] = c_d2[1];
    sredk[w][128 + p10]     = c_d2[2];
    sredk[w][128 + p10 + 1] = c_d2[3];
    __syncthreads();
    float s = 0.f;
#pragma unroll
    for (int ww = 0; ww < 8; ww++) s += sredk[ww][tid];
    g_part3[blockIdx.x][tid] = s;
}

// ---------------- K5: fused scores + online softmax + weighted sum ----------------
__global__ void __launch_bounds__(512, 2) k5_fused(const float* __restrict__ tok,
                                                   const float* __restrict__ gw) {
    extern __shared__ float smem[];
    float* s_gw     = smem;                       // 1024
    float* s_buf    = smem + 1024;                // 2 x 8192
    float* s_schalf = smem + 1024 + 2 * 8192;     // 16
    float* s_e      = s_schalf + 16;              // [SUBT][8]
    float* s_scale  = s_e + SUBT * 8;             // 8

    int c = blockIdx.x, b = blockIdx.y;
    int tid = threadIdx.x;
    int lane = tid & 31, w = tid >> 5;            // 16 warps
    const float* gtok = tok + ((size_t)b * N_ + (size_t)c * CH2) * D_;

    ((float2*)s_gw)[tid] = ((const float2*)gw)[tid];

    {
        unsigned dst = (unsigned)__cvta_generic_to_shared(s_buf) + tid * 16;
#pragma unroll
        for (int i = 0; i < 4; i++)
            CP_ASYNC16(dst + i * 512 * 16, (const float4*)gtok + tid + i * 512);
        CP_COMMIT();
    }

    float2 acc2[M_];
#pragma unroll
    for (int m = 0; m < M_; m++) acc2[m] = make_float2(0.f, 0.f);
    float rm = -3.0e38f, rs = 0.f;

    for (int t = 0; t < NSUB; t++) {
        float* buf = s_buf + (t & 1) * 8192;
        if (t + 1 < NSUB) {
            float* nbuf = s_buf + ((t + 1) & 1) * 8192;
            unsigned dst = (unsigned)__cvta_generic_to_shared(nbuf) + tid * 16;
            const float4* src = (const float4*)(gtok + (size_t)(t + 1) * SUBT * D_) + tid;
#pragma unroll
            for (int i = 0; i < 4; i++)
                CP_ASYNC16(dst + i * 512 * 16, src + i * 512);
            CP_COMMIT();
            CP_WAIT1();
        } else {
            CP_WAIT0();
        }
        __syncthreads();

        {
            int tok_j = w >> 1, half = w & 1;
            const float4* tp = (const float4*)(buf + (size_t)tok_j * D_ + half * 512);
            const float4* gp = (const float4*)(s_gw + half * 512);
            float acc = 0.f;
#pragma unroll
            for (int it = 0; it < 4; it++) {
                float4 a = tp[lane + it * 32];
                float4 g = gp[lane + it * 32];
                acc += a.x * g.x + a.y * g.y + a.z * g.z + a.w * g.w;
            }
#pragma unroll
            for (int o = 16; o; o >>= 1) acc += __shfl_down_sync(0xffffffffu, acc, o);
            if (lane == 0) s_schalf[w] = acc;
        }
        __syncthreads();

        if (w < 8) {
            int m = w;
            float v = -3.0e38f;
            if (lane < SUBT)
                v = s_schalf[2 * lane] + s_schalf[2 * lane + 1]
                  + g_logsoft[m * N_ + c * CH2 + t * SUBT + lane];
            float mx = v;
#pragma unroll
            for (int o = 16; o; o >>= 1) mx = fmaxf(mx, __shfl_xor_sync(0xffffffffu, mx, o));
            float nm = fmaxf(rm, mx);
            float sc = expf(rm - nm);
            float e = (lane < SUBT) ? expf(v - nm) : 0.f;
            if (lane < SUBT) s_e[lane * 8 + m] = e;
            float se = e;
#pragma unroll
            for (int o = 16; o; o >>= 1) se += __shfl_xor_sync(0xffffffffu, se, o);
            rs = rs * sc + se;
            rm = nm;
            if (lane == 0) s_scale[m] = sc;
        }
        __syncthreads();

        {
#pragma unroll
            for (int m = 0; m < M_; m++) {
                float sc = s_scale[m];
                acc2[m].x *= sc; acc2[m].y *= sc;
            }
#pragma unroll
            for (int j = 0; j < SUBT; j++) {
                float2 tv = *(const float2*)(buf + (size_t)j * D_ + tid * 2);
                float4 e0 = *(const float4*)(s_e + j * 8);
                float4 e1 = *(const float4*)(s_e + j * 8 + 4);
                acc2[0].x = fmaf(e0.x, tv.x, acc2[0].x); acc2[0].y = fmaf(e0.x, tv.y, acc2[0].y);
                acc2[1].x = fmaf(e0.y, tv.x, acc2[1].x); acc2[1].y = fmaf(e0.y, tv.y, acc2[1].y);
                acc2[2].x = fmaf(e0.z, tv.x, acc2[2].x); acc2[2].y = fmaf(e0.z, tv.y, acc2[2].y);
                acc2[3].x = fmaf(e0.w, tv.x, acc2[3].x); acc2[3].y = fmaf(e0.w, tv.y, acc2[3].y);
                acc2[4].x = fmaf(e1.x, tv.x, acc2[4].x); acc2[4].y = fmaf(e1.x, tv.y, acc2[4].y);
                acc2[5].x = fmaf(e1.y, tv.x, acc2[5].x); acc2[5].y = fmaf(e1.y, tv.y, acc2[5].y);
                acc2[6].x = fmaf(e1.z, tv.x, acc2[6].x); acc2[6].y = fmaf(e1.z, tv.y, acc2[6].y);
                acc2[7].x = fmaf(e1.w, tv.x, acc2[7].x); acc2[7].y = fmaf(e1.w, tv.y, acc2[7].y);
            }
        }
        __syncthreads();
    }

#pragma unroll
    for (int m = 0; m < M_; m++)
        *(float2*)&g_partial[(((size_t)c * M_ + m) * B_ + b) * D_ + tid * 2] = acc2[m];
    if (w < 8 && lane == 0) {
        int idx = (c * M_ + w) * B_ + b;
        g_locmax[idx] = rm;
        g_locsum[idx] = rs;
    }
}

// ---------------- K6: combine partials -> rgb out ----------------
__global__ void k6_combine(float* __restrict__ out) {
    int mb = blockIdx.x;
    int m = mb / B_, b = mb % B_;
    int tid = threadIdx.x;          // 256
    __shared__ float s_scale[NCH2];
    __shared__ float s_invS;
    if (tid == 0) {
        float MX = -1e30f;
#pragma unroll
        for (int c = 0; c < NCH2; c++)
            MX = fmaxf(MX, g_locmax[(c * M_ + m) * B_ + b]);
        float S = 0.f;
#pragma unroll
        for (int c = 0; c < NCH2; c++) {
            float sc = expf(g_locmax[(c * M_ + m) * B_ + b] - MX);
            s_scale[c] = sc;
            S += sc * g_locsum[(c * M_ + m) * B_ + b];
        }
        s_invS = 1.f / S;
    }
    __syncthreads();
    float4 a = make_float4(0.f, 0.f, 0.f, 0.f);
#pragma unroll
    for (int c = 0; c < NCH2; c++) {
        float sc = s_scale[c];
        float4 p = ((const float4*)&g_partial[(((size_t)c * M_ + m) * B_ + b) * D_])[tid];
        a.x = fmaf(sc, p.x, a.x);
        a.y = fmaf(sc, p.y, a.y);
        a.z = fmaf(sc, p.z, a.z);
        a.w = fmaf(sc, p.w, a.w);
    }
    float inv = s_invS;
    a.x *= inv; a.y *= inv; a.z *= inv; a.w *= inv;
    ((float4*)&out[((size_t)m * B_ + b) * D_])[tid] = a;
}

// ---------------- bilinear helpers ----------------
__device__ __forceinline__ float bilin_border(const float* img, float x, float y) {
    x = fminf(fmaxf(x, 0.f), (float)(W_ - 1));
    y = fminf(fmaxf(y, 0.f), (float)(H_ - 1));
    float x0f = floorf(x), y0f = floorf(y);
    float wx = x - x0f, wy = y - y0f;
    int x0 = (int)x0f, y0 = (int)y0f;
    int x1 = min(x0 + 1, W_ - 1), y1 = min(y0 + 1, H_ - 1);
    return img[y0 * W_ + x0] * (1.f - wx) * (1.f - wy)
         + img[y0 * W_ + x1] * wx * (1.f - wy)
         + img[y1 * W_ + x0] * (1.f - wx) * wy
         + img[y1 * W_ + x1] * wx * wy;
}

__device__ __forceinline__ float tap48(const float* img, int yy, int xx, float w) {
    if (xx >= 0 && xx < HV_ && yy >= 0 && yy < HV_) return img[yy * HV_ + xx] * w;
    return 0.f;
}

__device__ __forceinline__ float bilin_zeros48(const float* img, float x, float y) {
    float x0f = floorf(x), y0f = floorf(y);
    float wx = x - x0f, wy = y - y0f;
    int x0 = (int)x0f, y0 = (int)y0f;
    float v = tap48(img, y0, x0, (1.f - wx) * (1.f - wy));
    v += tap48(img, y0, x0 + 1, wx * (1.f - wy));
    v += tap48(img, y0 + 1, x0, (1.f - wx) * wy);
    v += tap48(img, y0 + 1, x0 + 1, wx * wy);
    return v;
}

// ---------------- K7: rays + stats + GEMV + layernorm ----------------
__global__ void k7_dep(const float* __restrict__ depth,
                       const float* __restrict__ dw, const float* __restrict__ db,
                       const float* __restrict__ gamma, const float* __restrict__ beta,
                       float* __restrict__ out) {
    int b = blockIdx.x, m = blockIdx.y;
    int tid = threadIdx.x;  // 512
    __shared__ float sm[32];
    __shared__ float s_stats[28];
    __shared__ float s_ds[NRAYS * NSAMP];
    __shared__ float s_sw[NRAYS * NSAMP];

    float a = 0.f, a2 = 0.f;
    if (tid < K3_BLOCKS) {
        a  = g_part3[tid][b * 8 + m];
        a2 = g_part3[tid][128 + b * 8 + m];
    }
    float sum_d  = blockSum(a, sm);
    float sum_d2 = blockSum(a2, sm);

    float count = g_msc[m * 8 + 0];
    float cx    = g_msc[m * 8 + 1];
    float cy    = g_msc[m * 8 + 2];
    float cxp   = g_msc[m * 8 + 3];
    float cyp   = g_msc[m * 8 + 4];

    float mean_d = sum_d / fmaxf(count, 1.f);
    float var = (sum_d2 - count * mean_d * mean_d) / fmaxf(count - 1.f, 1.f);
    float std_d = (count > 1.f) ? sqrtf(fmaxf(var, 0.f)) : 0.f;

    if (tid < NRAYS * NSAMP) {
        int r = tid / NSAMP, s = tid % NSAMP;
        double ang = (2.0 * 3.14159265358979323846 / (double)NRAYS) * (double)r;
        float ca = (float)cos(ang), sa = (float)sin(ang);
        float tv = (float)(((double)(W_ < H_ ? W_ : H_) * 0.45 / (double)(NSAMP - 1)) * (double)s);
        float x = cxp + ca * tv;
        float y = cyp + sa * tv;
        const float* dm = depth + (size_t)b * H_ * W_;
        s_ds[tid] = bilin_border(dm, x, y);
        float xp = x / (float)(W_ - 1) * (float)(HV_ - 1);
        float yp = y / (float)(H_ - 1) * (float)(HV_ - 1);
        float sw = bilin_zeros48(g_soft2d + m * N_, xp, yp);
        s_sw[tid] = fmaxf(sw, 1e-6f);
    }
    __syncthreads();

    if (tid < NRAYS) {
        float ws = 0.f, pr = 0.f;
#pragma unroll
        for (int s = 0; s < NSAMP; s++) {
            ws += s_sw[tid * NSAMP + s];
            pr += s_ds[tid * NSAMP + s] * s_sw[tid * NSAMP + s];
        }
        float ok = (count > 0.f) ? 1.f : 0.f;
        s_stats[4 + tid] = (pr / ws) * ok;
    }
    if (tid == 0) {
        float ok = (count > 0.f) ? 1.f : 0.f;
        s_stats[0] = mean_d * ok;
        s_stats[1] = std_d * ok;
        s_stats[2] = cx * ok;
        s_stats[3] = cy * ok;
    }
    __syncthreads();

    float h0 = db[tid], h1 = db[tid + 512];
#pragma unroll
    for (int k = 0; k < 28; k++) {
        float st = s_stats[k];
        h0 = fmaf(st, dw[k * D_ + tid], h0);
        h1 = fmaf(st, dw[k * D_ + tid + 512], h1);
    }
    float mu = blockSum(h0 + h1, sm) * (1.f / (float)D_);
    float e0 = h0 - mu, e1 = h1 - mu;
    float v2 = blockSum(e0 * e0 + e1 * e1, sm) * (1.f / (float)D_);
    float inv = rsqrtf(v2 + 1e-5f);
    size_t off = (size_t)(M_ * B_ * D_) + ((size_t)m * B_ + b) * D_;
    out[off + tid]       = e0 * inv * gamma[tid] + beta[tid];
    out[off + tid + 512] = e1 * inv * gamma[tid + 512] + beta[tid + 512];
}

// ---------------- launch ----------------
#define K5_SMEM ((1024 + 2 * 8192 + 16 + SUBT * 8 + 8) * 4)

extern "C" void kernel_launch(void* const* d_in, const int* in_sizes, int n_in,
                              void* d_out, int out_size) {
    const float* tok   = (const float*)d_in[0];
    const float* depth = (const float*)d_in[1];
    const int*   masks = (const int*)d_in[2];
    const float* gw    = (const float*)d_in[3];
    const float* dw    = (const float*)d_in[4];
    const float* db    = (const float*)d_in[5];
    const float* gamma = (const float*)d_in[6];
    const float* beta  = (const float*)d_in[7];
    float* out = (float*)d_out;

    cudaFuncSetAttribute(k5_fused, cudaFuncAttributeMaxDynamicSharedMemorySize, K5_SMEM);

    k2_mask<<<N_, 256>>>(masks);
    k2b_scalars<<<M_, 256>>>();
    k5_fused<<<dim3(NCH2, B_), 512, K5_SMEM>>>(tok, gw);
    k3_mma<<<K3_BLOCKS, 256>>>(depth);
    k6_combine<<<M_ * B_, 256>>>(out);
    k7_dep<<<dim3(B_, M_), 512>>>(depth, dw, db, gamma, beta, out);
}

// round 6
// speedup vs baseline: 1.2356x; 1.0385x over previous
#include <cuda_runtime.h>
#include <math.h>

#define B_ 16
#define N_ 2304
#define D_ 1024
#define H_ 1344
#define W_ 1344
#define M_ 8
#define HV_ 48
#define PH_ 28
#define NRAYS 24
#define NSAMP 20

#define NCH2 18           // chunks for rgb pass
#define CH2 128           // tokens per chunk
#define SUBT 8            // tokens per subtile
#define NSUB 16           // subtiles per chunk
#define K5_BLOCKS (NCH2 * B_)          // 288

#define K3_TILE 512
#define K3_TPB 8
#define K3_BLOCKS 441                  // 441*8*512 = H*W
#define SDP 516                        // padded row stride (floats)

// ---------------- scratch ----------------
__device__ unsigned char g_packed[H_ * W_];
__device__ int           g_patchsum[M_ * N_];
__device__ float         g_soft2d[M_ * N_];
__device__ float         g_logsoft[M_ * N_];
__device__ float         g_msc[M_ * 8];
__device__ float         g_part3[K3_BLOCKS][256];          // [type(2)][b(16)][m(8)]
__device__ float         g_partial[NCH2 * M_ * B_ * D_];   // 9.4 MB
__device__ float         g_locmax[NCH2 * M_ * B_];
__device__ float         g_locsum[NCH2 * M_ * B_];

// ---------------- helpers ----------------
__device__ __forceinline__ float blockSum(float v, float* sm) {
    int lane = threadIdx.x & 31, w = threadIdx.x >> 5;
    int nw = blockDim.x >> 5;
#pragma unroll
    for (int o = 16; o; o >>= 1) v += __shfl_down_sync(0xffffffffu, v, o);
    if (lane == 0) sm[w] = v;
    __syncthreads();
    if (w == 0) {
        v = (lane < nw) ? sm[lane] : 0.f;
#pragma unroll
        for (int o = 16; o; o >>= 1) v += __shfl_down_sync(0xffffffffu, v, o);
        if (lane == 0) sm[0] = v;
    }
    __syncthreads();
    float r = sm[0];
    __syncthreads();
    return r;
}

#define CP_ASYNC16(dst_smem_u32, src) \
    asm volatile("cp.async.cg.shared.global [%0], [%1], 16;" :: "r"(dst_smem_u32), "l"(src))
#define CP_ASYNC4(dst_smem_u32, src) \
    asm volatile("cp.async.ca.shared.global [%0], [%1], 4;" :: "r"(dst_smem_u32), "l"(src))
#define CP_COMMIT() asm volatile("cp.async.commit_group;")
#define CP_WAIT1() asm volatile("cp.async.wait_group 1;")
#define CP_WAIT0() asm volatile("cp.async.wait_group 0;")

__device__ __forceinline__ unsigned f2tf32(float f) {
    unsigned u;
    asm("cvt.rna.tf32.f32 %0, %1;" : "=r"(u) : "f"(f));
    return u;
}

__device__ __forceinline__ void mma_tf32(float* c, unsigned a0, unsigned a1,
                                         unsigned a2, unsigned a3,
                                         unsigned b0, unsigned b1) {
    asm volatile(
        "mma.sync.aligned.m16n8k8.row.col.f32.tf32.tf32.f32 "
        "{%0,%1,%2,%3}, {%4,%5,%6,%7}, {%8,%9}, {%0,%1,%2,%3};"
        : "+f"(c[0]), "+f"(c[1]), "+f"(c[2]), "+f"(c[3])
        : "r"(a0), "r"(a1), "r"(a2), "r"(a3), "r"(b0), "r"(b1));
}

// ---------------- K2: mask bitpack + per-patch sums ----------------
__global__ void k2_mask(const int* __restrict__ masks) {
    int p = blockIdx.x;
    int py = p / HV_, px = p % HV_;
    int tid = threadIdx.x;          // 256
    int sums[M_];
#pragma unroll
    for (int m = 0; m < M_; m++) sums[m] = 0;

    if (tid < 196) {
        int row = tid / 7, g = tid % 7;
        int y = py * PH_ + row;
        int x = px * PH_ + g * 4;
        unsigned b0 = 0, b1 = 0, b2 = 0, b3 = 0;
#pragma unroll
        for (int m = 0; m < M_; m++) {
            int4 v = *(const int4*)(masks + ((size_t)m * H_ + y) * W_ + x);
            int q0 = (v.x != 0), q1 = (v.y != 0), q2 = (v.z != 0), q3 = (v.w != 0);
            sums[m] = q0 + q1 + q2 + q3;
            b0 |= (unsigned)q0 << m; b1 |= (unsigned)q1 << m;
            b2 |= (unsigned)q2 << m; b3 |= (unsigned)q3 << m;
        }
        *(uchar4*)(g_packed + (size_t)y * W_ + x) =
            make_uchar4((unsigned char)b0, (unsigned char)b1, (unsigned char)b2, (unsigned char)b3);
    }

    __shared__ int ssum[8 * M_];
    int lane = tid & 31, w = tid >> 5;
#pragma unroll
    for (int m = 0; m < M_; m++) {
        int v = sums[m];
#pragma unroll
        for (int o = 16; o; o >>= 1) v += __shfl_down_sync(0xffffffffu, v, o);
        if (lane == 0) ssum[w * M_ + m] = v;
    }
    __syncthreads();
    if (tid < M_) {
        int t = 0;
#pragma unroll
        for (int ww = 0; ww < 8; ww++) t += ssum[ww * M_ + tid];
        g_patchsum[tid * N_ + p] = t;
    }
}

// ---------------- K2b: soft2d / logsoft / per-mask scalars ----------------
__global__ void k2b_scalars() {
    int m = blockIdx.x;
    int tid = threadIdx.x;  // 256
    __shared__ float sm[32];
    float c = 0.f, ss = 0.f, sx = 0.f, sy = 0.f;
    for (int p = tid; p < N_; p += 256) {
        int ps = g_patchsum[m * N_ + p];
        float cov = (float)ps * (1.f / 784.f);
        float soft = 1.f / (1.f + expf(-50.f * (cov - 0.3f)));
        g_soft2d[m * N_ + p] = soft;
        g_logsoft[m * N_ + p] = logf(fmaxf(soft, 1e-8f));
        c += (float)ps;
        ss += soft;
        sx += soft * (float)(p % HV_);
        sy += soft * (float)(p / HV_);
    }
    c  = blockSum(c, sm);
    ss = blockSum(ss, sm);
    sx = blockSum(sx, sm);
    sy = blockSum(sy, sm);
    if (tid == 0) {
        float soft_sum = ss + 1e-8f;
        float cx = sx / (soft_sum * (float)HV_);
        float cy = sy / (soft_sum * (float)HV_);
        g_msc[m * 8 + 0] = c;
        g_msc[m * 8 + 1] = cx;
        g_msc[m * 8 + 2] = cy;
        g_msc[m * 8 + 3] = cx * (float)(W_ - 1);
        g_msc[m * 8 + 4] = cy * (float)(H_ - 1);
    }
}

// ---------------- k3 device part: depth stats via tf32 MMA, cp.async pipeline ----------------
__device__ void k3_body(const float* __restrict__ depth, int k3id, float* smem) {
    // layout: sd0 [16][SDP], sd1 [16][SDP], smask0/1 (256 floats of bytes), sredk [16][256]
    float* sd[2] = {smem, smem + 16 * SDP};
    unsigned char* smask[2] = {(unsigned char*)(smem + 32 * SDP),
                               (unsigned char*)(smem + 32 * SDP) + K3_TILE};
    float* sredk = smem + 32 * SDP + 256;

    int tid = threadIdx.x;
    int lane = tid & 31, w = tid >> 5;    // 16 warps
    int gid = lane >> 2;                  // 0..7
    int tig = lane & 3;                   // 0..3

    float c_d[4]  = {0.f, 0.f, 0.f, 0.f};
    float c_d2[4] = {0.f, 0.f, 0.f, 0.f};

    // prologue: stage tile 0
    {
        size_t px0 = ((size_t)k3id * K3_TPB) * K3_TILE;
        unsigned base = (unsigned)__cvta_generic_to_shared(sd[0]);
#pragma unroll
        for (int i = 0; i < 4; i++) {
            int idx = tid + i * 512;
            int b = idx >> 7, g = idx & 127;
            CP_ASYNC16(base + (b * SDP + g * 4) * 4,
                       depth + (size_t)b * (H_ * W_) + px0 + g * 4);
        }
        if (tid < 128)
            CP_ASYNC4((unsigned)__cvta_generic_to_shared(smask[0]) + tid * 4,
                      g_packed + px0 + tid * 4);
        CP_COMMIT();
    }

    for (int t = 0; t < K3_TPB; t++) {
        CP_WAIT0();
        __syncthreads();                 // tile t staged; all warps past compute t-1
        if (t + 1 < K3_TPB) {            // stage tile t+1 into other buffer
            size_t px0 = ((size_t)k3id * K3_TPB + t + 1) * K3_TILE;
            int nb = (t + 1) & 1;
            unsigned base = (unsigned)__cvta_generic_to_shared(sd[nb]);
#pragma unroll
            for (int i = 0; i < 4; i++) {
                int idx = tid + i * 512;
                int b = idx >> 7, g = idx & 127;
                CP_ASYNC16(base + (b * SDP + g * 4) * 4,
                           depth + (size_t)b * (H_ * W_) + px0 + g * 4);
            }
            if (tid < 128)
                CP_ASYNC4((unsigned)__cvta_generic_to_shared(smask[nb]) + tid * 4,
                          g_packed + px0 + tid * 4);
            CP_COMMIT();
        }
        // compute tile t: warp w handles pixels [w*32, w*32+32) = 4 k-steps
        float* sdt = sd[t & 1];
        unsigned char* smt = smask[t & 1];
        int pbase = w * 32;
#pragma unroll
        for (int s = 0; s < 4; s++) {
            int px = pbase + s * 8;
            float a0 = sdt[gid * SDP + px + tig];
            float a1 = sdt[(gid + 8) * SDP + px + tig];
            float a2 = sdt[gid * SDP + px + 4 + tig];
            float a3 = sdt[(gid + 8) * SDP + px + 4 + tig];
            unsigned ua0 = f2tf32(a0), ua1 = f2tf32(a1), ua2 = f2tf32(a2), ua3 = f2tf32(a3);
            unsigned uq0 = f2tf32(a0 * a0), uq1 = f2tf32(a1 * a1);
            unsigned uq2 = f2tf32(a2 * a2), uq3 = f2tf32(a3 * a3);
            unsigned byt0 = smt[px + tig];
            unsigned byt1 = smt[px + 4 + tig];
            unsigned b0 = ((byt0 >> gid) & 1u) ? 0x3F800000u : 0u;
            unsigned b1 = ((byt1 >> gid) & 1u) ? 0x3F800000u : 0u;
            mma_tf32(c_d,  ua0, ua1, ua2, ua3, b0, b1);
            mma_tf32(c_d2, uq0, uq1, uq2, uq3, b0, b1);
        }
    }
    __syncthreads();

    // epilogue: fragment -> sredk -> cross-warp sum -> g_part3
    int p00 = gid * 8 + 2 * tig;
    int p10 = (gid + 8) * 8 + 2 * tig;
    sredk[w * 256 + p00]           = c_d[0];
    sredk[w * 256 + p00 + 1]       = c_d[1];
    sredk[w * 256 + p10]           = c_d[2];
    sredk[w * 256 + p10 + 1]       = c_d[3];
    sredk[w * 256 + 128 + p00]     = c_d2[0];
    sredk[w * 256 + 128 + p00 + 1] = c_d2[1];
    sredk[w * 256 + 128 + p10]     = c_d2[2];
    sredk[w * 256 + 128 + p10 + 1] = c_d2[3];
    __syncthreads();
    if (tid < 256) {
        float s = 0.f;
#pragma unroll
        for (int ww = 0; ww < 16; ww++) s += sredk[ww * 256 + tid];
        g_part3[k3id][tid] = s;
    }
}

// ---------------- k5 device part: fused scores + online softmax + weighted sum ----------------
__device__ void k5_body(const float* __restrict__ tok, const float* __restrict__ gw,
                        int c, int b, float* smem) {
    float* s_gw     = smem;                       // 1024
    float* s_buf    = smem + 1024;                // 2 x 8192
    float* s_schalf = smem + 1024 + 2 * 8192;     // 16
    float* s_e      = s_schalf + 16;              // [SUBT][8]
    float* s_scale  = s_e + SUBT * 8;             // 8

    int tid = threadIdx.x;
    int lane = tid & 31, w = tid >> 5;            // 16 warps
    const float* gtok = tok + ((size_t)b * N_ + (size_t)c * CH2) * D_;

    ((float2*)s_gw)[tid] = ((const float2*)gw)[tid];

    {
        unsigned dst = (unsigned)__cvta_generic_to_shared(s_buf) + tid * 16;
#pragma unroll
        for (int i = 0; i < 4; i++)
            CP_ASYNC16(dst + i * 512 * 16, (const float4*)gtok + tid + i * 512);
        CP_COMMIT();
    }

    float2 acc2[M_];
#pragma unroll
    for (int m = 0; m < M_; m++) acc2[m] = make_float2(0.f, 0.f);
    float rm = -3.0e38f, rs = 0.f;

    for (int t = 0; t < NSUB; t++) {
        float* buf = s_buf + (t & 1) * 8192;
        if (t + 1 < NSUB) {
            float* nbuf = s_buf + ((t + 1) & 1) * 8192;
            unsigned dst = (unsigned)__cvta_generic_to_shared(nbuf) + tid * 16;
            const float4* src = (const float4*)(gtok + (size_t)(t + 1) * SUBT * D_) + tid;
#pragma unroll
            for (int i = 0; i < 4; i++)
                CP_ASYNC16(dst + i * 512 * 16, src + i * 512);
            CP_COMMIT();
            CP_WAIT1();
        } else {
            CP_WAIT0();
        }
        __syncthreads();

        {
            int tok_j = w >> 1, half = w & 1;
            const float4* tp = (const float4*)(buf + (size_t)tok_j * D_ + half * 512);
            const float4* gp = (const float4*)(s_gw + half * 512);
            float acc = 0.f;
#pragma unroll
            for (int it = 0; it < 4; it++) {
                float4 a = tp[lane + it * 32];
                float4 g = gp[lane + it * 32];
                acc += a.x * g.x + a.y * g.y + a.z * g.z + a.w * g.w;
            }
#pragma unroll
            for (int o = 16; o; o >>= 1) acc += __shfl_down_sync(0xffffffffu, acc, o);
            if (lane == 0) s_schalf[w] = acc;
        }
        __syncthreads();

        if (w < 8) {
            int m = w;
            float v = -3.0e38f;
            if (lane < SUBT)
                v = s_schalf[2 * lane] + s_schalf[2 * lane + 1]
                  + g_logsoft[m * N_ + c * CH2 + t * SUBT + lane];
            float mx = v;
#pragma unroll
            for (int o = 16; o; o >>= 1) mx = fmaxf(mx, __shfl_xor_sync(0xffffffffu, mx, o));
            float nm = fmaxf(rm, mx);
            float sc = expf(rm - nm);
            float e = (lane < SUBT) ? expf(v - nm) : 0.f;
            if (lane < SUBT) s_e[lane * 8 + m] = e;
            float se = e;
#pragma unroll
            for (int o = 16; o; o >>= 1) se += __shfl_xor_sync(0xffffffffu, se, o);
            rs = rs * sc + se;
            rm = nm;
            if (lane == 0) s_scale[m] = sc;
        }
        __syncthreads();

        {
#pragma unroll
            for (int m = 0; m < M_; m++) {
                float sc = s_scale[m];
                acc2[m].x *= sc; acc2[m].y *= sc;
            }
#pragma unroll
            for (int j = 0; j < SUBT; j++) {
                float2 tv = *(const float2*)(buf + (size_t)j * D_ + tid * 2);
                float4 e0 = *(const float4*)(s_e + j * 8);
                float4 e1 = *(const float4*)(s_e + j * 8 + 4);
                acc2[0].x = fmaf(e0.x, tv.x, acc2[0].x); acc2[0].y = fmaf(e0.x, tv.y, acc2[0].y);
                acc2[1].x = fmaf(e0.y, tv.x, acc2[1].x); acc2[1].y = fmaf(e0.y, tv.y, acc2[1].y);
                acc2[2].x = fmaf(e0.z, tv.x, acc2[2].x); acc2[2].y = fmaf(e0.z, tv.y, acc2[2].y);
                acc2[3].x = fmaf(e0.w, tv.x, acc2[3].x); acc2[3].y = fmaf(e0.w, tv.y, acc2[3].y);
                acc2[4].x = fmaf(e1.x, tv.x, acc2[4].x); acc2[4].y = fmaf(e1.x, tv.y, acc2[4].y);
                acc2[5].x = fmaf(e1.y, tv.x, acc2[5].x); acc2[5].y = fmaf(e1.y, tv.y, acc2[5].y);
                acc2[6].x = fmaf(e1.z, tv.x, acc2[6].x); acc2[6].y = fmaf(e1.z, tv.y, acc2[6].y);
                acc2[7].x = fmaf(e1.w, tv.x, acc2[7].x); acc2[7].y = fmaf(e1.w, tv.y, acc2[7].y);
            }
        }
        __syncthreads();
    }

#pragma unroll
    for (int m = 0; m < M_; m++)
        *(float2*)&g_partial[(((size_t)c * M_ + m) * B_ + b) * D_ + tid * 2] = acc2[m];
    if (w < 8 && lane == 0) {
        int idx = (c * M_ + w) * B_ + b;
        g_locmax[idx] = rm;
        g_locsum[idx] = rs;
    }
}

// ---------------- K35: merged dispatch (288 k5 + 441 k3 interleaved) ----------------
__global__ void __launch_bounds__(512, 2) k35(const float* __restrict__ tok,
                                              const float* __restrict__ gw,
                                              const float* __restrict__ depth) {
    extern __shared__ float smem[];
    int bid = blockIdx.x;
    if (bid < 2 * K5_BLOCKS) {
        if ((bid & 1) == 0) {
            int id = bid >> 1;
            k5_body(tok, gw, id % NCH2, id / NCH2, smem);
        } else {
            k3_body(depth, bid >> 1, smem);
        }
    } else {
        k3_body(depth, K5_BLOCKS + (bid - 2 * K5_BLOCKS), smem);
    }
}

// ---------------- bilinear helpers ----------------
__device__ __forceinline__ float bilin_border(const float* img, float x, float y) {
    x = fminf(fmaxf(x, 0.f), (float)(W_ - 1));
    y = fminf(fmaxf(y, 0.f), (float)(H_ - 1));
    float x0f = floorf(x), y0f = floorf(y);
    float wx = x - x0f, wy = y - y0f;
    int x0 = (int)x0f, y0 = (int)y0f;
    int x1 = min(x0 + 1, W_ - 1), y1 = min(y0 + 1, H_ - 1);
    return img[y0 * W_ + x0] * (1.f - wx) * (1.f - wy)
         + img[y0 * W_ + x1] * wx * (1.f - wy)
         + img[y1 * W_ + x0] * (1.f - wx) * wy
         + img[y1 * W_ + x1] * wx * wy;
}

__device__ __forceinline__ float tap48(const float* img, int yy, int xx, float w) {
    if (xx >= 0 && xx < HV_ && yy >= 0 && yy < HV_) return img[yy * HV_ + xx] * w;
    return 0.f;
}

__device__ __forceinline__ float bilin_zeros48(const float* img, float x, float y) {
    float x0f = floorf(x), y0f = floorf(y);
    float wx = x - x0f, wy = y - y0f;
    int x0 = (int)x0f, y0 = (int)y0f;
    float v = tap48(img, y0, x0, (1.f - wx) * (1.f - wy));
    v += tap48(img, y0, x0 + 1, wx * (1.f - wy));
    v += tap48(img, y0 + 1, x0, (1.f - wx) * wy);
    v += tap48(img, y0 + 1, x0 + 1, wx * wy);
    return v;
}

// ---------------- K67: merged epilogue (128 dep blocks + 128 rgb blocks) ----------------
__global__ void __launch_bounds__(512) k67(const float* __restrict__ depth,
                                           const float* __restrict__ dw,
                                           const float* __restrict__ db,
                                           const float* __restrict__ gamma,
                                           const float* __restrict__ beta,
                                           float* __restrict__ out) {
    int bid = blockIdx.x;
    int tid = threadIdx.x;  // 512
    if (bid >= 128) {
        // ---- k6: combine rgb partials ----
        int mb = bid - 128;
        int m = mb / B_, b = mb % B_;
        __shared__ float s_scale[NCH2];
        __shared__ float s_invS;
        if (tid == 0) {
            float MX = -1e30f;
#pragma unroll
            for (int c = 0; c < NCH2; c++)
                MX = fmaxf(MX, g_locmax[(c * M_ + m) * B_ + b]);
            float S = 0.f;
#pragma unroll
            for (int c = 0; c < NCH2; c++) {
                float sc = expf(g_locmax[(c * M_ + m) * B_ + b] - MX);
                s_scale[c] = sc;
                S += sc * g_locsum[(c * M_ + m) * B_ + b];
            }
            s_invS = 1.f / S;
        }
        __syncthreads();
        float2 a = make_float2(0.f, 0.f);
#pragma unroll
        for (int c = 0; c < NCH2; c++) {
            float sc = s_scale[c];
            float2 p = *(const float2*)&g_partial[(((size_t)c * M_ + m) * B_ + b) * D_ + tid * 2];
            a.x = fmaf(sc, p.x, a.x);
            a.y = fmaf(sc, p.y, a.y);
        }
        float inv = s_invS;
        a.x *= inv; a.y *= inv;
        *(float2*)&out[((size_t)m * B_ + b) * D_ + tid * 2] = a;
        return;
    }

    // ---- k7: rays + stats + GEMV + layernorm ----
    int b = bid & 15, m = bid >> 4;
    __shared__ float sm[32];
    __shared__ float s_stats[28];
    __shared__ float s_ds[NRAYS * NSAMP];
    __shared__ float s_sw[NRAYS * NSAMP];

    float a = 0.f, a2 = 0.f;
    if (tid < K3_BLOCKS) {
        a  = g_part3[tid][b * 8 + m];
        a2 = g_part3[tid][128 + b * 8 + m];
    }
    float sum_d  = blockSum(a, sm);
    float sum_d2 = blockSum(a2, sm);

    float count = g_msc[m * 8 + 0];
    float cx    = g_msc[m * 8 + 1];
    float cy    = g_msc[m * 8 + 2];
    float cxp   = g_msc[m * 8 + 3];
    float cyp   = g_msc[m * 8 + 4];

    float mean_d = sum_d / fmaxf(count, 1.f);
    float var = (sum_d2 - count * mean_d * mean_d) / fmaxf(count - 1.f, 1.f);
    float std_d = (count > 1.f) ? sqrtf(fmaxf(var, 0.f)) : 0.f;

    if (tid < NRAYS * NSAMP) {
        int r = tid / NSAMP, s = tid % NSAMP;
        double ang = (2.0 * 3.14159265358979323846 / (double)NRAYS) * (double)r;
        float ca = (float)cos(ang), sa = (float)sin(ang);
        float tv = (float)(((double)(W_ < H_ ? W_ : H_) * 0.45 / (double)(NSAMP - 1)) * (double)s);
        float x = cxp + ca * tv;
        float y = cyp + sa * tv;
        const float* dm = depth + (size_t)b * H_ * W_;
        s_ds[tid] = bilin_border(dm, x, y);
        float xp = x / (float)(W_ - 1) * (float)(HV_ - 1);
        float yp = y / (float)(H_ - 1) * (float)(HV_ - 1);
        float sw = bilin_zeros48(g_soft2d + m * N_, xp, yp);
        s_sw[tid] = fmaxf(sw, 1e-6f);
    }
    __syncthreads();

    if (tid < NRAYS) {
        float ws = 0.f, pr = 0.f;
#pragma unroll
        for (int s = 0; s < NSAMP; s++) {
            ws += s_sw[tid * NSAMP + s];
            pr += s_ds[tid * NSAMP + s] * s_sw[tid * NSAMP + s];
        }
        float ok = (count > 0.f) ? 1.f : 0.f;
        s_stats[4 + tid] = (pr / ws) * ok;
    }
    if (tid == 0) {
        float ok = (count > 0.f) ? 1.f : 0.f;
        s_stats[0] = mean_d * ok;
        s_stats[1] = std_d * ok;
        s_stats[2] = cx * ok;
        s_stats[3] = cy * ok;
    }
    __syncthreads();

    float h0 = db[tid], h1 = db[tid + 512];
#pragma unroll
    for (int k = 0; k < 28; k++) {
        float st = s_stats[k];
        h0 = fmaf(st, dw[k * D_ + tid], h0);
        h1 = fmaf(st, dw[k * D_ + tid + 512], h1);
    }
    float mu = blockSum(h0 + h1, sm) * (1.f / (float)D_);
    float e0 = h0 - mu, e1 = h1 - mu;
    float v2 = blockSum(e0 * e0 + e1 * e1, sm) * (1.f / (float)D_);
    float inv = rsqrtf(v2 + 1e-5f);
    size_t off = (size_t)(M_ * B_ * D_) + ((size_t)m * B_ + b) * D_;
    out[off + tid]       = e0 * inv * gamma[tid] + beta[tid];
    out[off + tid + 512] = e1 * inv * gamma[tid + 512] + beta[tid + 512];
}

// ---------------- launch ----------------
// union smem: k5 needs (1024 + 16384 + 16 + 64 + 8) floats = 69,984 B
//             k3 needs (32*SDP + 256 + 16*256) floats = 83,456 B
#define K35_SMEM 84000

extern "C" void kernel_launch(void* const* d_in, const int* in_sizes, int n_in,
                              void* d_out, int out_size) {
    const float* tok   = (const float*)d_in[0];
    const float* depth = (const float*)d_in[1];
    const int*   masks = (const int*)d_in[2];
    const float* gw    = (const float*)d_in[3];
    const float* dw    = (const float*)d_in[4];
    const float* db    = (const float*)d_in[5];
    const float* gamma = (const float*)d_in[6];
    const float* beta  = (const float*)d_in[7];
    float* out = (float*)d_out;

    cudaFuncSetAttribute(k35, cudaFuncAttributeMaxDynamicSharedMemorySize, K35_SMEM);

    k2_mask<<<N_, 256>>>(masks);
    k2b_scalars<<<M_, 256>>>();
    k35<<<2 * K5_BLOCKS + (K3_BLOCKS - K5_BLOCKS), 512, K35_SMEM>>>(tok, gw, depth);
    k67<<<256, 512>>>(depth, dw, db, gamma, beta, out);
}